// round 1
// baseline (speedup 1.0000x reference)
#include <cuda_runtime.h>

// Problem constants: B=2, S=T=2048, E=1024, H=16, D=64 (MQA, 1 KV head)

__device__ float g_q [(size_t)2 * 2048 * 1024];  // scaled Q projection [B,T,E]
__device__ float g_k [(size_t)2 * 2048 * 64];    // K projection [B,S,D]
__device__ float g_v [(size_t)2 * 2048 * 64];    // V projection [B,S,D]
__device__ float g_ao[(size_t)2 * 2048 * 1024];  // attention output [B,T,E]

// ---------------------------------------------------------------------------
// Generic C[M,N] = alpha * (A[M,K] @ W[N,K]^T + bias[N])   (both row-major, NT)
// 128x128 block tile, BK=8, 256 threads, 8x8 microtile.
// Requires: M % 128 == 0, K % 8 == 0. N may be < 128 (guarded).
// ---------------------------------------------------------------------------
#define GBM 128
#define GBN 128
#define GBK 8
#define GLD (GBM + 4)   // padded leading dim: 132 (multiple of 4 -> float4-aligned rows)

__global__ __launch_bounds__(256) void gemm_nt_bias(
    const float* __restrict__ A, const float* __restrict__ W,
    const float* __restrict__ bias, float* __restrict__ C,
    int M, int N, int K, float alpha)
{
    __shared__ float As[GBK][GLD];
    __shared__ float Ws[GBK][GLD];

    const int tid = threadIdx.x;
    const int tx = tid & 15;
    const int ty = tid >> 4;
    const int m0 = blockIdx.y * GBM;
    const int n0 = blockIdx.x * GBN;

    const int lr = tid >> 1;        // 0..127 (row within tile)
    const int lc = (tid & 1) * 4;   // 0 or 4 (float4 column within BK=8)

    float acc[8][8];
#pragma unroll
    for (int i = 0; i < 8; i++)
#pragma unroll
        for (int j = 0; j < 8; j++) acc[i][j] = 0.f;

    for (int k0 = 0; k0 < K; k0 += GBK) {
        float4 av = *reinterpret_cast<const float4*>(A + (size_t)(m0 + lr) * K + k0 + lc);
        float4 wv = make_float4(0.f, 0.f, 0.f, 0.f);
        if (n0 + lr < N)
            wv = *reinterpret_cast<const float4*>(W + (size_t)(n0 + lr) * K + k0 + lc);

        As[lc + 0][lr] = av.x; As[lc + 1][lr] = av.y;
        As[lc + 2][lr] = av.z; As[lc + 3][lr] = av.w;
        Ws[lc + 0][lr] = wv.x; Ws[lc + 1][lr] = wv.y;
        Ws[lc + 2][lr] = wv.z; Ws[lc + 3][lr] = wv.w;
        __syncthreads();

#pragma unroll
        for (int k = 0; k < GBK; k++) {
            float4 a0 = *reinterpret_cast<const float4*>(&As[k][ty * 8]);
            float4 a1 = *reinterpret_cast<const float4*>(&As[k][ty * 8 + 4]);
            float4 w0 = *reinterpret_cast<const float4*>(&Ws[k][tx * 8]);
            float4 w1 = *reinterpret_cast<const float4*>(&Ws[k][tx * 8 + 4]);
            float a[8] = {a0.x, a0.y, a0.z, a0.w, a1.x, a1.y, a1.z, a1.w};
            float w[8] = {w0.x, w0.y, w0.z, w0.w, w1.x, w1.y, w1.z, w1.w};
#pragma unroll
            for (int i = 0; i < 8; i++)
#pragma unroll
                for (int j = 0; j < 8; j++)
                    acc[i][j] = fmaf(a[i], w[j], acc[i][j]);
        }
        __syncthreads();
    }

#pragma unroll
    for (int i = 0; i < 8; i++) {
        const int m = m0 + ty * 8 + i;
#pragma unroll
        for (int j = 0; j < 8; j++) {
            const int n = n0 + tx * 8 + j;
            if (n < N)
                C[(size_t)m * N + n] = alpha * (acc[i][j] + bias[n]);
        }
    }
}

// ---------------------------------------------------------------------------
// Fused MQA attention with online softmax.
// Grid: (T/128, H, B). Block: 256 threads as 16x16 (ty, tx).
// Thread owns 8 query rows (ty*8..+7) and 4 columns (tx*4..+3).
// Q is pre-scaled by D^-0.5. K/V are the shared single head [B,S,64].
// Output written directly in [B, T, H*D] layout for the O projection.
// ---------------------------------------------------------------------------
__global__ __launch_bounds__(256) void attn_kernel(
    const float* __restrict__ Q, const float* __restrict__ Kp,
    const float* __restrict__ Vp, float* __restrict__ O)
{
    extern __shared__ float sm[];
    float* Qs = sm;                  // [128][65]
    float* Ks = Qs + 128 * 65;       // [64][65]
    float* Vs = Ks + 64 * 65;        // [64][64]
    float* Ps = Vs + 64 * 64;        // [128][65]

    const int b = blockIdx.z, h = blockIdx.y;
    const int t0 = blockIdx.x * 128;
    const int tid = threadIdx.x;
    const int tx = tid & 15, ty = tid >> 4;

    const float* Qb = Q + ((size_t)(b * 2048 + t0)) * 1024 + h * 64;
    const float* Kb = Kp + (size_t)b * 2048 * 64;
    const float* Vb = Vp + (size_t)b * 2048 * 64;

    // Load the 128x64 Q tile (scaled) into shared.
    for (int e = tid; e < 128 * 16; e += 256) {
        int r = e >> 4, c = (e & 15) << 2;
        float4 t4 = *reinterpret_cast<const float4*>(Qb + (size_t)r * 1024 + c);
        Qs[r * 65 + c + 0] = t4.x; Qs[r * 65 + c + 1] = t4.y;
        Qs[r * 65 + c + 2] = t4.z; Qs[r * 65 + c + 3] = t4.w;
    }

    float m_i[8], l_i[8], oacc[8][4];
#pragma unroll
    for (int i = 0; i < 8; i++) {
        m_i[i] = -1e30f; l_i[i] = 0.f;
#pragma unroll
        for (int j = 0; j < 4; j++) oacc[i][j] = 0.f;
    }

    for (int s0 = 0; s0 < 2048; s0 += 64) {
        __syncthreads();  // protect Ks/Vs (prev PV GEMM) before overwrite
        for (int e = tid; e < 64 * 16; e += 256) {
            int r = e >> 4, c = (e & 15) << 2;
            float4 k4 = *reinterpret_cast<const float4*>(Kb + (size_t)(s0 + r) * 64 + c);
            Ks[r * 65 + c + 0] = k4.x; Ks[r * 65 + c + 1] = k4.y;
            Ks[r * 65 + c + 2] = k4.z; Ks[r * 65 + c + 3] = k4.w;
            float4 v4 = *reinterpret_cast<const float4*>(Vb + (size_t)(s0 + r) * 64 + c);
            *reinterpret_cast<float4*>(Vs + r * 64 + c) = v4;
        }
        __syncthreads();

        // S tile = Q_tile @ K_tile^T  (thread: 8x4 microtile)
        float st[8][4];
#pragma unroll
        for (int i = 0; i < 8; i++)
#pragma unroll
            for (int j = 0; j < 4; j++) st[i][j] = 0.f;

#pragma unroll 8
        for (int k = 0; k < 64; k++) {
            float a[8], kk[4];
#pragma unroll
            for (int i = 0; i < 8; i++) a[i] = Qs[(ty * 8 + i) * 65 + k];
#pragma unroll
            for (int j = 0; j < 4; j++) kk[j] = Ks[(tx * 4 + j) * 65 + k];
#pragma unroll
            for (int i = 0; i < 8; i++)
#pragma unroll
                for (int j = 0; j < 4; j++)
                    st[i][j] = fmaf(a[i], kk[j], st[i][j]);
        }

        // Online softmax: row reductions across the 16 tx lanes (same ty).
#pragma unroll
        for (int i = 0; i < 8; i++) {
            float mx = fmaxf(fmaxf(st[i][0], st[i][1]), fmaxf(st[i][2], st[i][3]));
#pragma unroll
            for (int off = 8; off > 0; off >>= 1)
                mx = fmaxf(mx, __shfl_xor_sync(0xffffffffu, mx, off));
            const float mnew = fmaxf(m_i[i], mx);
            const float corr = __expf(m_i[i] - mnew);
            m_i[i] = mnew;
            float rs = 0.f;
#pragma unroll
            for (int j = 0; j < 4; j++) {
                st[i][j] = __expf(st[i][j] - mnew);
                rs += st[i][j];
            }
#pragma unroll
            for (int off = 8; off > 0; off >>= 1)
                rs += __shfl_xor_sync(0xffffffffu, rs, off);
            l_i[i] = l_i[i] * corr + rs;
#pragma unroll
            for (int j = 0; j < 4; j++) {
                oacc[i][j] *= corr;
                Ps[(ty * 8 + i) * 65 + tx * 4 + j] = st[i][j];
            }
        }
        __syncthreads();

        // O += P_tile @ V_tile   (thread: rows ty*8..+7, dims tx*4..+3)
#pragma unroll 8
        for (int k = 0; k < 64; k++) {
            float p[8];
#pragma unroll
            for (int i = 0; i < 8; i++) p[i] = Ps[(ty * 8 + i) * 65 + k];
            const float4 v4 = *reinterpret_cast<const float4*>(Vs + k * 64 + tx * 4);
#pragma unroll
            for (int i = 0; i < 8; i++) {
                oacc[i][0] = fmaf(p[i], v4.x, oacc[i][0]);
                oacc[i][1] = fmaf(p[i], v4.y, oacc[i][1]);
                oacc[i][2] = fmaf(p[i], v4.z, oacc[i][2]);
                oacc[i][3] = fmaf(p[i], v4.w, oacc[i][3]);
            }
        }
    }

    float* Ob = O + ((size_t)(b * 2048 + t0)) * 1024 + h * 64;
#pragma unroll
    for (int i = 0; i < 8; i++) {
        const float inv = 1.f / l_i[i];
#pragma unroll
        for (int j = 0; j < 4; j++)
            Ob[(size_t)(ty * 8 + i) * 1024 + tx * 4 + j] = oacc[i][j] * inv;
    }
}

// ---------------------------------------------------------------------------
extern "C" void kernel_launch(void* const* d_in, const int* in_sizes, int n_in,
                              void* d_out, int out_size)
{
    const float* query = (const float*)d_in[0];
    const float* key   = (const float*)d_in[1];
    const float* value = (const float*)d_in[2];
    const float* Wq    = (const float*)d_in[3];
    const float* bq    = (const float*)d_in[4];
    const float* Wk    = (const float*)d_in[5];
    const float* bk    = (const float*)d_in[6];
    const float* Wv    = (const float*)d_in[7];
    const float* bv    = (const float*)d_in[8];
    const float* Wo    = (const float*)d_in[9];
    const float* bo    = (const float*)d_in[10];
    float* out = (float*)d_out;

    float *q, *k, *v, *ao;
    cudaGetSymbolAddress((void**)&q,  g_q);
    cudaGetSymbolAddress((void**)&k,  g_k);
    cudaGetSymbolAddress((void**)&v,  g_v);
    cudaGetSymbolAddress((void**)&ao, g_ao);

    const int M = 2 * 2048;   // B * T
    const dim3 blk(256);

    // Q projection with D^-0.5 folded in
    gemm_nt_bias<<<dim3(1024 / GBN, M / GBM), blk>>>(query, Wq, bq, q, M, 1024, 1024, 0.125f);
    // K / V projections (N = 64)
    gemm_nt_bias<<<dim3(1, M / GBM), blk>>>(key,   Wk, bk, k, M, 64, 1024, 1.0f);
    gemm_nt_bias<<<dim3(1, M / GBM), blk>>>(value, Wv, bv, v, M, 64, 1024, 1.0f);

    // Fused attention
    const int ATT_SMEM = (128 * 65 + 64 * 65 + 64 * 64 + 128 * 65) * (int)sizeof(float);
    cudaFuncSetAttribute(attn_kernel, cudaFuncAttributeMaxDynamicSharedMemorySize, ATT_SMEM);
    attn_kernel<<<dim3(2048 / 128, 16, 2), blk, ATT_SMEM>>>(q, k, v, ao);

    // Output projection straight into d_out
    gemm_nt_bias<<<dim3(1024 / GBN, M / GBM), blk>>>(ao, Wo, bo, out, M, 1024, 1024, 1.0f);
}

// round 2
// speedup vs baseline: 2.2028x; 2.2028x over previous
#include <cuda_runtime.h>
#include <cstdint>

// Problem constants: B=2, S=T=2048, E=1024, H=16, D=64 (MQA, 1 KV head)

__device__ float g_q [(size_t)2 * 2048 * 1024];  // scaled Q projection [B,T,E]
__device__ float g_k [(size_t)2 * 2048 * 64];    // K projection [B,S,D]
__device__ float g_v [(size_t)2 * 2048 * 64];    // V projection [B,S,D]
__device__ float g_ao[(size_t)2 * 2048 * 1024];  // attention output [B,T,E]

__device__ __forceinline__ uint32_t f2t(float x) {
    uint32_t r;
    asm("cvt.rna.tf32.f32 %0, %1;" : "=r"(r) : "f"(x));
    return r;
}

// D(16x8,f32) += A(16x8,tf32,row) @ B(8x8,tf32,col)
__device__ __forceinline__ void mma8(float c[4], const uint32_t a[4], const uint32_t b[2]) {
    asm volatile(
        "mma.sync.aligned.m16n8k8.row.col.f32.tf32.tf32.f32 "
        "{%0,%1,%2,%3},{%4,%5,%6,%7},{%8,%9},{%0,%1,%2,%3};"
        : "+f"(c[0]), "+f"(c[1]), "+f"(c[2]), "+f"(c[3])
        : "r"(a[0]), "r"(a[1]), "r"(a[2]), "r"(a[3]), "r"(b[0]), "r"(b[1]));
}

// ---------------------------------------------------------------------------
// C[M,N] = alpha * (A[M,K] @ W[N,K]^T + bias[N])  via tf32 mma.
// Block tile 128x128, BK=32, 256 threads (8 warps as 2m x 4n).
// Warp tile 64x32 (4 m-tiles of 16, 4 n-tiles of 8). LD=36 -> conflict-free frags.
// ---------------------------------------------------------------------------
#define TLD 36

__global__ __launch_bounds__(256) void gemm_tf32(
    const float* __restrict__ A, const float* __restrict__ W,
    const float* __restrict__ bias, float* __restrict__ C,
    int M, int N, int K, float alpha)
{
    __shared__ uint32_t As[128 * TLD];
    __shared__ uint32_t Ws[128 * TLD];

    const int tid  = threadIdx.x;
    const int lane = tid & 31;
    const int wid  = tid >> 5;
    const int wm   = wid >> 2;      // 0..1
    const int wn   = wid & 3;       // 0..3
    const int g    = lane >> 2;     // 0..7
    const int tg   = lane & 3;      // 0..3
    const int m0   = blockIdx.y * 128;
    const int n0   = blockIdx.x * 128;

    const int lr = tid >> 1;            // 0..127 (tile row to load)
    const int lc = (tid & 1) * 16;      // 0 or 16 (col offset, 4 float4s)

    float acc[4][4][4] = {};

    const float* Arow = A + (size_t)(m0 + lr) * K + lc;
    const bool   wok  = (n0 + lr) < N;
    const float* Wrow = W + (size_t)(wok ? (n0 + lr) : 0) * K + lc;

    for (int k0 = 0; k0 < K; k0 += 32) {
        float4 av[4], wv[4];
#pragma unroll
        for (int j = 0; j < 4; j++) {
            av[j] = *reinterpret_cast<const float4*>(Arow + k0 + 4 * j);
            float4 t = *reinterpret_cast<const float4*>(Wrow + k0 + 4 * j);
            wv[j] = wok ? t : make_float4(0.f, 0.f, 0.f, 0.f);
        }
        __syncthreads();
#pragma unroll
        for (int j = 0; j < 4; j++) {
            uint4 ua = make_uint4(f2t(av[j].x), f2t(av[j].y), f2t(av[j].z), f2t(av[j].w));
            uint4 uw = make_uint4(f2t(wv[j].x), f2t(wv[j].y), f2t(wv[j].z), f2t(wv[j].w));
            *reinterpret_cast<uint4*>(&As[lr * TLD + lc + 4 * j]) = ua;
            *reinterpret_cast<uint4*>(&Ws[lr * TLD + lc + 4 * j]) = uw;
        }
        __syncthreads();

#pragma unroll
        for (int kk = 0; kk < 4; kk++) {
            const int kb = kk * 8;
            uint32_t af[4][4], bf[4][2];
#pragma unroll
            for (int mt = 0; mt < 4; mt++) {
                const int rb = wm * 64 + mt * 16;
                af[mt][0] = As[(rb + g)     * TLD + kb + tg];
                af[mt][1] = As[(rb + 8 + g) * TLD + kb + tg];
                af[mt][2] = As[(rb + g)     * TLD + kb + tg + 4];
                af[mt][3] = As[(rb + 8 + g) * TLD + kb + tg + 4];
            }
#pragma unroll
            for (int nt = 0; nt < 4; nt++) {
                const int nb = wn * 32 + nt * 8;
                bf[nt][0] = Ws[(nb + g) * TLD + kb + tg];
                bf[nt][1] = Ws[(nb + g) * TLD + kb + tg + 4];
            }
#pragma unroll
            for (int mt = 0; mt < 4; mt++)
#pragma unroll
                for (int nt = 0; nt < 4; nt++)
                    mma8(acc[mt][nt], af[mt], bf[nt]);
        }
    }

#pragma unroll
    for (int mt = 0; mt < 4; mt++) {
        const int r0 = m0 + wm * 64 + mt * 16 + g;
#pragma unroll
        for (int nt = 0; nt < 4; nt++) {
            const int col = n0 + wn * 32 + nt * 8 + 2 * tg;
            if (col < N) {
                const float b0 = bias[col], b1 = bias[col + 1];
                float2 o0 = make_float2(alpha * (acc[mt][nt][0] + b0),
                                        alpha * (acc[mt][nt][1] + b1));
                float2 o1 = make_float2(alpha * (acc[mt][nt][2] + b0),
                                        alpha * (acc[mt][nt][3] + b1));
                *reinterpret_cast<float2*>(C + (size_t)r0 * N + col)       = o0;
                *reinterpret_cast<float2*>(C + (size_t)(r0 + 8) * N + col) = o1;
            }
        }
    }
}

// ---------------------------------------------------------------------------
// Fused MQA flash attention, tf32 tensor cores.
// Grid (T/64, H, B), 128 threads (4 warps). Warp w owns query rows [16w,16w+16).
// Q frags preloaded to registers; Q smem buffer reused for P.
// Smem tiles LD=68 words -> conflict-free fragment access.
// ---------------------------------------------------------------------------
#define ALD 68

__global__ __launch_bounds__(128) void attn_tc(
    const float* __restrict__ Q, const float* __restrict__ Kp,
    const float* __restrict__ Vp, float* __restrict__ O)
{
    extern __shared__ uint32_t sm[];
    uint32_t* Ps = sm;                 // 64 x ALD (Q tile first, then P tile)
    uint32_t* Ks = sm + 64 * ALD;      // 64(s) x ALD(k=d)
    uint32_t* Vs = sm + 2 * 64 * ALD;  // 64(d) x ALD(s)  (transposed V)

    const int b  = blockIdx.z, h = blockIdx.y;
    const int t0 = blockIdx.x * 64;
    const int tid  = threadIdx.x;
    const int lane = tid & 31;
    const int w    = tid >> 5;
    const int g    = lane >> 2;
    const int tg   = lane & 3;
    const int rb   = w * 16;

    const float* Qb = Q + (size_t)(b * 2048 + t0) * 1024 + h * 64;
    const float* Kb = Kp + (size_t)b * 2048 * 64;
    const float* Vb = Vp + (size_t)b * 2048 * 64;

    // Load Q tile (warp-local rows: thread tid writes row tid/2)
#pragma unroll
    for (int i = 0; i < 8; i++) {
        const int e = tid * 8 + i;
        const int r = e >> 4, c = (e & 15) * 4;
        float4 q4 = *reinterpret_cast<const float4*>(Qb + (size_t)r * 1024 + c);
        *reinterpret_cast<uint4*>(&Ps[r * ALD + c]) =
            make_uint4(f2t(q4.x), f2t(q4.y), f2t(q4.z), f2t(q4.w));
    }
    __syncwarp();

    // Preload all Q fragments (Q reused across every K-tile)
    uint32_t qa[8][4];
#pragma unroll
    for (int kk = 0; kk < 8; kk++) {
        const int kb = kk * 8;
        qa[kk][0] = Ps[(rb + g)     * ALD + kb + tg];
        qa[kk][1] = Ps[(rb + 8 + g) * ALD + kb + tg];
        qa[kk][2] = Ps[(rb + g)     * ALD + kb + tg + 4];
        qa[kk][3] = Ps[(rb + 8 + g) * ALD + kb + tg + 4];
    }

    float m_[2] = {-1e30f, -1e30f};
    float l_[2] = {0.f, 0.f};
    float oacc[8][4] = {};

    for (int s0 = 0; s0 < 2048; s0 += 64) {
        // Prefetch K/V tiles into registers (overlaps barrier wait)
        float4 k4[8], v4[8];
#pragma unroll
        for (int i = 0; i < 8; i++) {
            const int e = tid * 8 + i;
            const int r = e >> 4, c = (e & 15) * 4;
            k4[i] = *reinterpret_cast<const float4*>(Kb + (size_t)(s0 + r) * 64 + c);
            v4[i] = *reinterpret_cast<const float4*>(Vb + (size_t)(s0 + r) * 64 + c);
        }
        __syncthreads();   // prior tile's mma reads of Ks/Vs complete
#pragma unroll
        for (int i = 0; i < 8; i++) {
            const int e = tid * 8 + i;
            const int r = e >> 4, c = (e & 15) * 4;
            *reinterpret_cast<uint4*>(&Ks[r * ALD + c]) =
                make_uint4(f2t(k4[i].x), f2t(k4[i].y), f2t(k4[i].z), f2t(k4[i].w));
            Vs[(c + 0) * ALD + r] = f2t(v4[i].x);
            Vs[(c + 1) * ALD + r] = f2t(v4[i].y);
            Vs[(c + 2) * ALD + r] = f2t(v4[i].z);
            Vs[(c + 3) * ALD + r] = f2t(v4[i].w);
        }
        __syncthreads();

        // S = Q @ K^T   (warp: 16 x 64)
        float sf[8][4] = {};
#pragma unroll
        for (int kk = 0; kk < 8; kk++) {
            const int kb = kk * 8;
#pragma unroll
            for (int nt = 0; nt < 8; nt++) {
                uint32_t bf[2];
                bf[0] = Ks[(nt * 8 + g) * ALD + kb + tg];
                bf[1] = Ks[(nt * 8 + g) * ALD + kb + tg + 4];
                mma8(sf[nt], qa[kk], bf);
            }
        }

        // Online softmax; thread holds rows rb+g (regs 0,1) and rb+8+g (regs 2,3)
#pragma unroll
        for (int half = 0; half < 2; half++) {
            const int i0 = half * 2;
            float mx = -1e30f;
#pragma unroll
            for (int nt = 0; nt < 8; nt++)
                mx = fmaxf(mx, fmaxf(sf[nt][i0], sf[nt][i0 + 1]));
            mx = fmaxf(mx, __shfl_xor_sync(0xffffffffu, mx, 1));
            mx = fmaxf(mx, __shfl_xor_sync(0xffffffffu, mx, 2));
            const float mnew = fmaxf(m_[half], mx);
            const float corr = __expf(m_[half] - mnew);
            m_[half] = mnew;
            float sum = 0.f;
#pragma unroll
            for (int nt = 0; nt < 8; nt++) {
                float p0 = __expf(sf[nt][i0] - mnew);
                float p1 = __expf(sf[nt][i0 + 1] - mnew);
                sf[nt][i0] = p0; sf[nt][i0 + 1] = p1;
                sum += p0 + p1;
            }
            sum += __shfl_xor_sync(0xffffffffu, sum, 1);
            sum += __shfl_xor_sync(0xffffffffu, sum, 2);
            l_[half] = l_[half] * corr + sum;
#pragma unroll
            for (int nt = 0; nt < 8; nt++) {
                oacc[nt][i0]     *= corr;
                oacc[nt][i0 + 1] *= corr;
            }
        }

        // Store P (warp-local rows) as tf32
#pragma unroll
        for (int nt = 0; nt < 8; nt++) {
            const int cb = nt * 8 + 2 * tg;
            *reinterpret_cast<uint2*>(&Ps[(rb + g) * ALD + cb]) =
                make_uint2(f2t(sf[nt][0]), f2t(sf[nt][1]));
            *reinterpret_cast<uint2*>(&Ps[(rb + 8 + g) * ALD + cb]) =
                make_uint2(f2t(sf[nt][2]), f2t(sf[nt][3]));
        }
        __syncwarp();

        // O += P @ V   (k = s dim, n = d dim)
#pragma unroll
        for (int kk = 0; kk < 8; kk++) {
            const int kb = kk * 8;
            uint32_t pa[4];
            pa[0] = Ps[(rb + g)     * ALD + kb + tg];
            pa[1] = Ps[(rb + 8 + g) * ALD + kb + tg];
            pa[2] = Ps[(rb + g)     * ALD + kb + tg + 4];
            pa[3] = Ps[(rb + 8 + g) * ALD + kb + tg + 4];
#pragma unroll
            for (int nt = 0; nt < 8; nt++) {
                uint32_t bf[2];
                bf[0] = Vs[(nt * 8 + g) * ALD + kb + tg];
                bf[1] = Vs[(nt * 8 + g) * ALD + kb + tg + 4];
                mma8(oacc[nt], pa, bf);
            }
        }
    }

    // Epilogue: normalize and write O in [B,T,H*D] layout
    const float inv0 = 1.f / l_[0];
    const float inv1 = 1.f / l_[1];
    float* Ob = O + (size_t)(b * 2048 + t0) * 1024 + h * 64;
#pragma unroll
    for (int nt = 0; nt < 8; nt++) {
        const int col = nt * 8 + 2 * tg;
        *reinterpret_cast<float2*>(Ob + (size_t)(rb + g) * 1024 + col) =
            make_float2(oacc[nt][0] * inv0, oacc[nt][1] * inv0);
        *reinterpret_cast<float2*>(Ob + (size_t)(rb + 8 + g) * 1024 + col) =
            make_float2(oacc[nt][2] * inv1, oacc[nt][3] * inv1);
    }
}

// ---------------------------------------------------------------------------
extern "C" void kernel_launch(void* const* d_in, const int* in_sizes, int n_in,
                              void* d_out, int out_size)
{
    const float* query = (const float*)d_in[0];
    const float* key   = (const float*)d_in[1];
    const float* value = (const float*)d_in[2];
    const float* Wq    = (const float*)d_in[3];
    const float* bq    = (const float*)d_in[4];
    const float* Wk    = (const float*)d_in[5];
    const float* bk    = (const float*)d_in[6];
    const float* Wv    = (const float*)d_in[7];
    const float* bv    = (const float*)d_in[8];
    const float* Wo    = (const float*)d_in[9];
    const float* bo    = (const float*)d_in[10];
    float* out = (float*)d_out;

    float *q, *k, *v, *ao;
    cudaGetSymbolAddress((void**)&q,  g_q);
    cudaGetSymbolAddress((void**)&k,  g_k);
    cudaGetSymbolAddress((void**)&v,  g_v);
    cudaGetSymbolAddress((void**)&ao, g_ao);

    const int M = 2 * 2048;

    // Projections (Q has D^-0.5 folded in)
    gemm_tf32<<<dim3(8, 32), 256>>>(query, Wq, bq, q, M, 1024, 1024, 0.125f);
    gemm_tf32<<<dim3(1, 32), 256>>>(key,   Wk, bk, k, M, 64, 1024, 1.0f);
    gemm_tf32<<<dim3(1, 32), 256>>>(value, Wv, bv, v, M, 64, 1024, 1.0f);

    // Fused attention
    const int ATT_SMEM = 3 * 64 * ALD * (int)sizeof(uint32_t);
    cudaFuncSetAttribute(attn_tc, cudaFuncAttributeMaxDynamicSharedMemorySize, ATT_SMEM);
    attn_tc<<<dim3(2048 / 64, 16, 2), 128, ATT_SMEM>>>(q, k, v, ao);

    // Output projection straight into d_out
    gemm_tf32<<<dim3(8, 32), 256>>>(ao, Wo, bo, out, M, 1024, 1024, 1.0f);
}